// round 1
// baseline (speedup 1.0000x reference)
#include <cuda_runtime.h>
#include <math.h>

// Problem constants
#define B_SZ   2
#define T_SEQ  2048
#define E_DIM  2048
#define NH     16
#define NKV    8
#define HD     128
#define ROWS   (B_SZ * T_SEQ)        // 4096
#define QW     (NH * HD)             // 2048
#define KW     (NKV * HD)            // 1024

// Scratch (static device globals; no dynamic allocation allowed)
__device__ float g_Q[(size_t)ROWS * QW];     // 32 MB
__device__ float g_K[(size_t)ROWS * KW];     // 16 MB
__device__ float g_V[(size_t)ROWS * KW];     // 16 MB
__device__ float g_AO[(size_t)ROWS * QW];    // 32 MB
__device__ float g_cos[T_SEQ * (HD / 2)];
__device__ float g_sin[T_SEQ * (HD / 2)];

// ---------------------------------------------------------------------------
// SGEMM: C[M,N] = A[M,K] @ B[K,N], row-major, M%128==0, N%128==0, K%8==0
// 128x128 block tile, BK=8, 256 threads, 8x8 micro-tile per thread.
// ---------------------------------------------------------------------------
__global__ __launch_bounds__(256) void sgemm128(
    const float* __restrict__ A, const float* __restrict__ B,
    float* __restrict__ C, int M, int N, int K)
{
    __shared__ float As[8][128];
    __shared__ float Bs[8][128];

    const int tid = threadIdx.x;
    const int bx = blockIdx.x, by = blockIdx.y;

    const float* Ab = A + (size_t)(by * 128) * K;
    const float* Bb = B + bx * 128;

    const int arow = tid >> 1;            // 0..127
    const int acol = (tid & 1) * 4;       // 0 or 4
    const int brow = tid >> 5;            // 0..7
    const int bcol = (tid & 31) << 2;     // 0..124 step 4

    const int tx = tid & 15;              // col group
    const int ty = tid >> 4;              // row group

    float acc[8][8];
#pragma unroll
    for (int i = 0; i < 8; i++)
#pragma unroll
        for (int j = 0; j < 8; j++) acc[i][j] = 0.f;

    for (int k0 = 0; k0 < K; k0 += 8) {
        __syncthreads();
        float4 av = *(const float4*)(Ab + (size_t)arow * K + k0 + acol);
        As[acol + 0][arow] = av.x;
        As[acol + 1][arow] = av.y;
        As[acol + 2][arow] = av.z;
        As[acol + 3][arow] = av.w;
        *(float4*)(&Bs[brow][bcol]) = *(const float4*)(Bb + (size_t)(k0 + brow) * N + bcol);
        __syncthreads();

#pragma unroll
        for (int kk = 0; kk < 8; kk++) {
            float a[8], bb[8];
            *(float4*)(a)     = *(const float4*)(&As[kk][ty * 8]);
            *(float4*)(a + 4) = *(const float4*)(&As[kk][ty * 8 + 4]);
            *(float4*)(bb)     = *(const float4*)(&Bs[kk][tx * 8]);
            *(float4*)(bb + 4) = *(const float4*)(&Bs[kk][tx * 8 + 4]);
#pragma unroll
            for (int i = 0; i < 8; i++)
#pragma unroll
                for (int j = 0; j < 8; j++)
                    acc[i][j] = fmaf(a[i], bb[j], acc[i][j]);
        }
    }

    float* Cb = C + (size_t)(by * 128 + ty * 8) * N + bx * 128 + tx * 8;
#pragma unroll
    for (int i = 0; i < 8; i++) {
        float4 c0 = make_float4(acc[i][0], acc[i][1], acc[i][2], acc[i][3]);
        float4 c1 = make_float4(acc[i][4], acc[i][5], acc[i][6], acc[i][7]);
        *(float4*)(Cb + (size_t)i * N)     = c0;
        *(float4*)(Cb + (size_t)i * N + 4) = c1;
    }
}

// ---------------------------------------------------------------------------
// RoPE table: cos/sin in double precision (more accurate than fp32 reference;
// difference well below the 1e-3 tolerance)
// ---------------------------------------------------------------------------
__global__ void rope_table_kernel()
{
    int idx = blockIdx.x * blockDim.x + threadIdx.x;
    if (idx >= T_SEQ * (HD / 2)) return;
    int t = idx / (HD / 2);
    int i = idx % (HD / 2);
    double inv = pow(10000.0, -(double)(2 * i) / (double)HD);
    double ang = (double)t * inv;
    double s, c;
    sincos(ang, &s, &c);
    g_cos[idx] = (float)c;
    g_sin[idx] = (float)s;
}

// Apply RoPE in-place to tensor with layout (B*T, nheads*128)
__global__ void rope_apply_kernel(float* __restrict__ x, int nheads)
{
    int idx = blockIdx.x * blockDim.x + threadIdx.x;
    int pairs_per_row = nheads * (HD / 2);
    if (idx >= ROWS * pairs_per_row) return;
    int row = idx / pairs_per_row;
    int p = idx - row * pairs_per_row;
    int h = p / (HD / 2);
    int i = p - h * (HD / 2);
    int t = row & (T_SEQ - 1);
    float c = g_cos[t * (HD / 2) + i];
    float s = g_sin[t * (HD / 2) + i];
    float* base = x + (size_t)row * nheads * HD + h * HD + 2 * i;
    float x0 = base[0], x1 = base[1];
    base[0] = x0 * c - x1 * s;
    base[1] = x0 * s + x1 * c;
}

// ---------------------------------------------------------------------------
// Flash attention, fp32, causal, GQA (2 q heads per kv head).
// Block: 256 threads = 8 warps; 32 q-rows per block (4 rows/warp, 8 lanes/row,
// each lane owns 16 of the 128 dims). K/V tiles 32x128 staged in smem.
// Tile-level online softmax: logits shfl-reduced, per-tile max/rescale.
// ---------------------------------------------------------------------------
__global__ __launch_bounds__(256) void attn_kernel()
{
    __shared__ float Ks[32 * 128];
    __shared__ float Vs[32 * 128];

    const int tid = threadIdx.x;
    const int w = tid >> 5, lane = tid & 31;
    const int rl = (w << 2) + (lane >> 3);   // local q row 0..31
    const int g = lane & 7;                  // 16-dim group 0..7

    const int qb = blockIdx.x;               // q tile index
    const int bh = blockIdx.y;
    const int b = bh >> 4, h = bh & 15;
    const int kh = h >> 1;                   // GQA: kv head
    const int qi = qb * 32 + rl;

    const float scale = 0.08838834764831845f;  // 128^-0.5

    float q[16], o[16];
    const float* qptr = g_Q + (size_t)(b * T_SEQ + qi) * QW + h * HD + g * 16;
#pragma unroll
    for (int j = 0; j < 16; j++) { q[j] = qptr[j] * scale; o[j] = 0.f; }

    float m = -INFINITY, l = 0.f;

    for (int t0 = 0; t0 <= qb; t0++) {
        const int k0 = t0 * 32;
        const float* Kb = g_K + (size_t)(b * T_SEQ + k0) * KW + kh * HD;
        const float* Vb = g_V + (size_t)(b * T_SEQ + k0) * KW + kh * HD;

        __syncthreads();
#pragma unroll
        for (int it = 0; it < 4; it++) {
            int idx = tid + it * 256;        // float4 index 0..1023
            int r = idx >> 5;
            int c = idx & 31;
            ((float4*)Ks)[idx] = *(const float4*)(Kb + (size_t)r * KW + c * 4);
            ((float4*)Vs)[idx] = *(const float4*)(Vb + (size_t)r * KW + c * 4);
        }
        __syncthreads();

        const bool diag = (t0 == qb);
        float sreg[4];
        float tmax = -INFINITY;

        // Phase 1: logits (all lanes end with full dot for every kk)
#pragma unroll
        for (int kk = 0; kk < 32; kk++) {
            const float4* kr = (const float4*)(Ks + kk * 128 + g * 16);
            float4 ka = kr[0], kb2 = kr[1], kc = kr[2], kd = kr[3];
            float s;
            s = q[0] * ka.x;
            s = fmaf(q[1],  ka.y,  s); s = fmaf(q[2],  ka.z,  s); s = fmaf(q[3],  ka.w,  s);
            s = fmaf(q[4],  kb2.x, s); s = fmaf(q[5],  kb2.y, s); s = fmaf(q[6],  kb2.z, s); s = fmaf(q[7],  kb2.w, s);
            s = fmaf(q[8],  kc.x,  s); s = fmaf(q[9],  kc.y,  s); s = fmaf(q[10], kc.z,  s); s = fmaf(q[11], kc.w,  s);
            s = fmaf(q[12], kd.x,  s); s = fmaf(q[13], kd.y,  s); s = fmaf(q[14], kd.z,  s); s = fmaf(q[15], kd.w,  s);
            s += __shfl_xor_sync(0xffffffffu, s, 1);
            s += __shfl_xor_sync(0xffffffffu, s, 2);
            s += __shfl_xor_sync(0xffffffffu, s, 4);
            if (diag && (k0 + kk > qi)) s = -INFINITY;
            if ((kk & 7) == g) sreg[kk >> 3] = s;
            tmax = fmaxf(tmax, s);
        }

        // Tile-level rescale
        float mnew = fmaxf(m, tmax);
        float corr = __expf(m - mnew);   // first tile: exp(-inf) = 0
        l *= corr;
#pragma unroll
        for (int j = 0; j < 16; j++) o[j] *= corr;
        m = mnew;

        // Phase 2: P @ V
#pragma unroll
        for (int kk = 0; kk < 32; kk++) {
            float s = __shfl_sync(0xffffffffu, sreg[kk >> 3], kk & 7, 8);
            float p = __expf(s - m);
            l += p;
            const float4* vr = (const float4*)(Vs + kk * 128 + g * 16);
            float4 va = vr[0], vb2 = vr[1], vc = vr[2], vd = vr[3];
            o[0]  = fmaf(p, va.x,  o[0]);  o[1]  = fmaf(p, va.y,  o[1]);
            o[2]  = fmaf(p, va.z,  o[2]);  o[3]  = fmaf(p, va.w,  o[3]);
            o[4]  = fmaf(p, vb2.x, o[4]);  o[5]  = fmaf(p, vb2.y, o[5]);
            o[6]  = fmaf(p, vb2.z, o[6]);  o[7]  = fmaf(p, vb2.w, o[7]);
            o[8]  = fmaf(p, vc.x,  o[8]);  o[9]  = fmaf(p, vc.y,  o[9]);
            o[10] = fmaf(p, vc.z,  o[10]); o[11] = fmaf(p, vc.w,  o[11]);
            o[12] = fmaf(p, vd.x,  o[12]); o[13] = fmaf(p, vd.y,  o[13]);
            o[14] = fmaf(p, vd.z,  o[14]); o[15] = fmaf(p, vd.w,  o[15]);
        }
    }

    const float inv = 1.f / l;
    float* outp = g_AO + (size_t)(b * T_SEQ + qi) * QW + h * HD + g * 16;
#pragma unroll
    for (int v4 = 0; v4 < 4; v4++) {
        float4 ov = make_float4(o[v4 * 4 + 0] * inv, o[v4 * 4 + 1] * inv,
                                o[v4 * 4 + 2] * inv, o[v4 * 4 + 3] * inv);
        *(float4*)(outp + v4 * 4) = ov;
    }
}

// ---------------------------------------------------------------------------
// kernel_launch: x, mask, wq, wk, wv, wo -> out (B,T,E) fp32
// ---------------------------------------------------------------------------
extern "C" void kernel_launch(void* const* d_in, const int* in_sizes, int n_in,
                              void* d_out, int out_size)
{
    const float* x  = (const float*)d_in[0];
    // d_in[1] = causal mask (unused: causality computed directly)
    const float* wq = (const float*)d_in[2];
    const float* wk = (const float*)d_in[3];
    const float* wv = (const float*)d_in[4];
    const float* wo = (const float*)d_in[5];
    float* out = (float*)d_out;

    float *Qp, *Kp, *Vp, *AOp;
    cudaGetSymbolAddress((void**)&Qp,  g_Q);
    cudaGetSymbolAddress((void**)&Kp,  g_K);
    cudaGetSymbolAddress((void**)&Vp,  g_V);
    cudaGetSymbolAddress((void**)&AOp, g_AO);

    // QKV projections
    {
        dim3 grid(QW / 128, ROWS / 128);
        sgemm128<<<grid, 256>>>(x, wq, Qp, ROWS, QW, E_DIM);
    }
    {
        dim3 grid(KW / 128, ROWS / 128);
        sgemm128<<<grid, 256>>>(x, wk, Kp, ROWS, KW, E_DIM);
        sgemm128<<<grid, 256>>>(x, wv, Vp, ROWS, KW, E_DIM);
    }

    // RoPE
    {
        int n = T_SEQ * (HD / 2);
        rope_table_kernel<<<(n + 255) / 256, 256>>>();
        int nq = ROWS * NH * (HD / 2);
        rope_apply_kernel<<<(nq + 255) / 256, 256>>>(Qp, NH);
        int nk = ROWS * NKV * (HD / 2);
        rope_apply_kernel<<<(nk + 255) / 256, 256>>>(Kp, NKV);
    }

    // Attention
    {
        dim3 grid(T_SEQ / 32, B_SZ * NH);
        attn_kernel<<<grid, 256>>>();
    }

    // Output projection
    {
        dim3 grid(E_DIM / 128, ROWS / 128);
        sgemm128<<<grid, 256>>>(AOp, wo, out, ROWS, E_DIM, E_DIM);
    }
}

// round 2
// speedup vs baseline: 1.1329x; 1.1329x over previous
#include <cuda_runtime.h>
#include <math.h>
#include <stdint.h>

// Problem constants
#define B_SZ   2
#define T_SEQ  2048
#define E_DIM  2048
#define NH     16
#define NKV    8
#define HD     128
#define ROWS   (B_SZ * T_SEQ)        // 4096
#define QW     (NH * HD)             // 2048
#define KW     (NKV * HD)            // 1024

// Scratch (static device globals; no dynamic allocation allowed)
__device__ float g_Q[(size_t)ROWS * QW];     // 32 MB
__device__ float g_K[(size_t)ROWS * KW];     // 16 MB
__device__ float g_V[(size_t)ROWS * KW];     // 16 MB
__device__ float g_AO[(size_t)ROWS * QW];    // 32 MB
__device__ float g_cos[T_SEQ * (HD / 2)];
__device__ float g_sin[T_SEQ * (HD / 2)];

// ---------------------------------------------------------------------------
// TF32 helpers
// ---------------------------------------------------------------------------
__device__ __forceinline__ float to_tf32(float x) {
    uint32_t u;
    asm("cvt.rna.tf32.f32 %0, %1;" : "=r"(u) : "f"(x));
    return __uint_as_float(u);
}

__device__ __forceinline__ void mma_tf32(float* d, const uint32_t* a, const uint32_t* b) {
    asm volatile(
        "mma.sync.aligned.m16n8k8.row.col.f32.tf32.tf32.f32 "
        "{%0,%1,%2,%3}, {%4,%5,%6,%7}, {%8,%9}, {%0,%1,%2,%3};\n"
        : "+f"(d[0]), "+f"(d[1]), "+f"(d[2]), "+f"(d[3])
        : "r"(a[0]), "r"(a[1]), "r"(a[2]), "r"(a[3]), "r"(b[0]), "r"(b[1]));
}

// ---------------------------------------------------------------------------
// TF32 tensor-core GEMM: C[M,N] = A[M,K] @ B[K,N], row-major.
// 128x128 block tile, BK=16, 256 threads (8 warps, each 32x64 via m16n8k8).
// Double-buffered smem, cvt-to-tf32 at staging, conflict-free pads.
// Requires M%128==0, N%128==0, K%16==0.
// ---------------------------------------------------------------------------
#define GBK 16
#define A_LD 20     // As row pitch (floats): (lane/4)*20 + lane%4 distinct mod 32
#define B_LD 136    // Bs row pitch (floats): (lane%4)*136 + lane/4 distinct mod 32

__global__ __launch_bounds__(256) void gemm_tf32(
    const float* __restrict__ A, const float* __restrict__ B,
    float* __restrict__ C, int M, int N, int K)
{
    __shared__ float As[2][128 * A_LD];
    __shared__ float Bs[2][GBK * B_LD];

    const int tid = threadIdx.x;
    const int bx = blockIdx.x, by = blockIdx.y;
    const int warp = tid >> 5, lane = tid & 31;
    const int wm = (warp >> 1) * 32;   // warp m offset within 128
    const int wn = (warp & 1) * 64;    // warp n offset within 128
    const int lq = lane >> 2;          // 0..7
    const int lr = lane & 3;           // 0..3

    // Global load mapping
    const int ar = tid >> 2;            // A rows 0..63 (and +64)
    const int ac = (tid & 3) * 4;       // A cols 0,4,8,12
    const int br = tid >> 5;            // B rows 0..7 (and +8)
    const int bc = (tid & 31) * 4;      // B cols 0..124

    const float* Ag = A + (size_t)(by * 128 + ar) * K + ac;
    const float* Bg = B + (size_t)br * N + bx * 128 + bc;

    float4 a0g = *(const float4*)(Ag);
    float4 a1g = *(const float4*)(Ag + (size_t)64 * K);
    float4 b0g = *(const float4*)(Bg);
    float4 b1g = *(const float4*)(Bg + (size_t)8 * N);

    float acc[2][8][4];
#pragma unroll
    for (int mi = 0; mi < 2; mi++)
#pragma unroll
        for (int ni = 0; ni < 8; ni++)
#pragma unroll
            for (int j = 0; j < 4; j++) acc[mi][ni][j] = 0.f;

    const int nk = K / GBK;
    int buf = 0;

    for (int kt = 0; kt < nk; kt++) {
        float* as = As[buf];
        float* bs = Bs[buf];

        // cvt + STS
        {
            float* p = as + ar * A_LD + ac;
            p[0] = to_tf32(a0g.x); p[1] = to_tf32(a0g.y); p[2] = to_tf32(a0g.z); p[3] = to_tf32(a0g.w);
            p = as + (ar + 64) * A_LD + ac;
            p[0] = to_tf32(a1g.x); p[1] = to_tf32(a1g.y); p[2] = to_tf32(a1g.z); p[3] = to_tf32(a1g.w);
            p = bs + br * B_LD + bc;
            p[0] = to_tf32(b0g.x); p[1] = to_tf32(b0g.y); p[2] = to_tf32(b0g.z); p[3] = to_tf32(b0g.w);
            p = bs + (br + 8) * B_LD + bc;
            p[0] = to_tf32(b1g.x); p[1] = to_tf32(b1g.y); p[2] = to_tf32(b1g.z); p[3] = to_tf32(b1g.w);
        }
        __syncthreads();

        // Prefetch next tile (latency hidden by MMA compute below)
        if (kt + 1 < nk) {
            const float* Ag2 = Ag + (kt + 1) * GBK;
            const float* Bg2 = Bg + (size_t)(kt + 1) * GBK * N;
            a0g = *(const float4*)(Ag2);
            a1g = *(const float4*)(Ag2 + (size_t)64 * K);
            b0g = *(const float4*)(Bg2);
            b1g = *(const float4*)(Bg2 + (size_t)8 * N);
        }

        // Compute: 2 k8-steps
#pragma unroll
        for (int k8 = 0; k8 < GBK; k8 += 8) {
            uint32_t af[2][4];
            uint32_t bf[8][2];
#pragma unroll
            for (int mi = 0; mi < 2; mi++) {
                const int m = wm + mi * 16 + lq;
                af[mi][0] = __float_as_uint(as[m * A_LD + k8 + lr]);
                af[mi][1] = __float_as_uint(as[(m + 8) * A_LD + k8 + lr]);
                af[mi][2] = __float_as_uint(as[m * A_LD + k8 + lr + 4]);
                af[mi][3] = __float_as_uint(as[(m + 8) * A_LD + k8 + lr + 4]);
            }
#pragma unroll
            for (int ni = 0; ni < 8; ni++) {
                const int n = wn + ni * 8 + lq;
                bf[ni][0] = __float_as_uint(bs[(k8 + lr) * B_LD + n]);
                bf[ni][1] = __float_as_uint(bs[(k8 + lr + 4) * B_LD + n]);
            }
#pragma unroll
            for (int mi = 0; mi < 2; mi++)
#pragma unroll
                for (int ni = 0; ni < 8; ni++)
                    mma_tf32(acc[mi][ni], af[mi], bf[ni]);
        }

        buf ^= 1;
        __syncthreads();
    }

    // Epilogue
    float* Cb = C + (size_t)(by * 128) * N + bx * 128;
#pragma unroll
    for (int mi = 0; mi < 2; mi++) {
#pragma unroll
        for (int ni = 0; ni < 8; ni++) {
            const int r = wm + mi * 16 + lq;
            const int c = wn + ni * 8 + lr * 2;
            float2 v0 = make_float2(acc[mi][ni][0], acc[mi][ni][1]);
            float2 v1 = make_float2(acc[mi][ni][2], acc[mi][ni][3]);
            *(float2*)(Cb + (size_t)r * N + c) = v0;
            *(float2*)(Cb + (size_t)(r + 8) * N + c) = v1;
        }
    }
}

// ---------------------------------------------------------------------------
// RoPE table: cos/sin in double precision
// ---------------------------------------------------------------------------
__global__ void rope_table_kernel()
{
    int idx = blockIdx.x * blockDim.x + threadIdx.x;
    if (idx >= T_SEQ * (HD / 2)) return;
    int t = idx / (HD / 2);
    int i = idx % (HD / 2);
    double inv = pow(10000.0, -(double)(2 * i) / (double)HD);
    double ang = (double)t * inv;
    double s, c;
    sincos(ang, &s, &c);
    g_cos[idx] = (float)c;
    g_sin[idx] = (float)s;
}

// Apply RoPE in-place to tensor with layout (B*T, nheads*128)
__global__ void rope_apply_kernel(float* __restrict__ x, int nheads)
{
    int idx = blockIdx.x * blockDim.x + threadIdx.x;
    int pairs_per_row = nheads * (HD / 2);
    if (idx >= ROWS * pairs_per_row) return;
    int row = idx / pairs_per_row;
    int p = idx - row * pairs_per_row;
    int h = p / (HD / 2);
    int i = p - h * (HD / 2);
    int t = row & (T_SEQ - 1);
    float c = g_cos[t * (HD / 2) + i];
    float s = g_sin[t * (HD / 2) + i];
    float* base = x + (size_t)row * nheads * HD + h * HD + 2 * i;
    float x0 = base[0], x1 = base[1];
    base[0] = x0 * c - x1 * s;
    base[1] = x0 * s + x1 * c;
}

// ---------------------------------------------------------------------------
// Flash attention, fp32, causal, GQA (2 q heads per kv head).
// ---------------------------------------------------------------------------
__global__ __launch_bounds__(256) void attn_kernel()
{
    __shared__ float Ks[32 * 128];
    __shared__ float Vs[32 * 128];

    const int tid = threadIdx.x;
    const int w = tid >> 5, lane = tid & 31;
    const int rl = (w << 2) + (lane >> 3);   // local q row 0..31
    const int g = lane & 7;                  // 16-dim group 0..7

    const int qb = blockIdx.x;               // q tile index
    const int bh = blockIdx.y;
    const int b = bh >> 4, h = bh & 15;
    const int kh = h >> 1;                   // GQA: kv head
    const int qi = qb * 32 + rl;

    const float scale = 0.08838834764831845f;  // 128^-0.5

    float q[16], o[16];
    const float* qptr = g_Q + (size_t)(b * T_SEQ + qi) * QW + h * HD + g * 16;
#pragma unroll
    for (int j = 0; j < 16; j++) { q[j] = qptr[j] * scale; o[j] = 0.f; }

    float m = -INFINITY, l = 0.f;

    for (int t0 = 0; t0 <= qb; t0++) {
        const int k0 = t0 * 32;
        const float* Kb = g_K + (size_t)(b * T_SEQ + k0) * KW + kh * HD;
        const float* Vb = g_V + (size_t)(b * T_SEQ + k0) * KW + kh * HD;

        __syncthreads();
#pragma unroll
        for (int it = 0; it < 4; it++) {
            int idx = tid + it * 256;        // float4 index 0..1023
            int r = idx >> 5;
            int c = idx & 31;
            ((float4*)Ks)[idx] = *(const float4*)(Kb + (size_t)r * KW + c * 4);
            ((float4*)Vs)[idx] = *(const float4*)(Vb + (size_t)r * KW + c * 4);
        }
        __syncthreads();

        const bool diag = (t0 == qb);
        float sreg[4];
        float tmax = -INFINITY;

#pragma unroll
        for (int kk = 0; kk < 32; kk++) {
            const float4* kr = (const float4*)(Ks + kk * 128 + g * 16);
            float4 ka = kr[0], kb2 = kr[1], kc = kr[2], kd = kr[3];
            float s;
            s = q[0] * ka.x;
            s = fmaf(q[1],  ka.y,  s); s = fmaf(q[2],  ka.z,  s); s = fmaf(q[3],  ka.w,  s);
            s = fmaf(q[4],  kb2.x, s); s = fmaf(q[5],  kb2.y, s); s = fmaf(q[6],  kb2.z, s); s = fmaf(q[7],  kb2.w, s);
            s = fmaf(q[8],  kc.x,  s); s = fmaf(q[9],  kc.y,  s); s = fmaf(q[10], kc.z,  s); s = fmaf(q[11], kc.w,  s);
            s = fmaf(q[12], kd.x,  s); s = fmaf(q[13], kd.y,  s); s = fmaf(q[14], kd.z,  s); s = fmaf(q[15], kd.w,  s);
            s += __shfl_xor_sync(0xffffffffu, s, 1);
            s += __shfl_xor_sync(0xffffffffu, s, 2);
            s += __shfl_xor_sync(0xffffffffu, s, 4);
            if (diag && (k0 + kk > qi)) s = -INFINITY;
            if ((kk & 7) == g) sreg[kk >> 3] = s;
            tmax = fmaxf(tmax, s);
        }

        float mnew = fmaxf(m, tmax);
        float corr = __expf(m - mnew);
        l *= corr;
#pragma unroll
        for (int j = 0; j < 16; j++) o[j] *= corr;
        m = mnew;

#pragma unroll
        for (int kk = 0; kk < 32; kk++) {
            float s = __shfl_sync(0xffffffffu, sreg[kk >> 3], kk & 7, 8);
            float p = __expf(s - m);
            l += p;
            const float4* vr = (const float4*)(Vs + kk * 128 + g * 16);
            float4 va = vr[0], vb2 = vr[1], vc = vr[2], vd = vr[3];
            o[0]  = fmaf(p, va.x,  o[0]);  o[1]  = fmaf(p, va.y,  o[1]);
            o[2]  = fmaf(p, va.z,  o[2]);  o[3]  = fmaf(p, va.w,  o[3]);
            o[4]  = fmaf(p, vb2.x, o[4]);  o[5]  = fmaf(p, vb2.y, o[5]);
            o[6]  = fmaf(p, vb2.z, o[6]);  o[7]  = fmaf(p, vb2.w, o[7]);
            o[8]  = fmaf(p, vc.x,  o[8]);  o[9]  = fmaf(p, vc.y,  o[9]);
            o[10] = fmaf(p, vc.z,  o[10]); o[11] = fmaf(p, vc.w,  o[11]);
            o[12] = fmaf(p, vd.x,  o[12]); o[13] = fmaf(p, vd.y,  o[13]);
            o[14] = fmaf(p, vd.z,  o[14]); o[15] = fmaf(p, vd.w,  o[15]);
        }
    }

    const float inv = 1.f / l;
    float* outp = g_AO + (size_t)(b * T_SEQ + qi) * QW + h * HD + g * 16;
#pragma unroll
    for (int v4 = 0; v4 < 4; v4++) {
        float4 ov = make_float4(o[v4 * 4 + 0] * inv, o[v4 * 4 + 1] * inv,
                                o[v4 * 4 + 2] * inv, o[v4 * 4 + 3] * inv);
        *(float4*)(outp + v4 * 4) = ov;
    }
}

// ---------------------------------------------------------------------------
// kernel_launch: x, mask, wq, wk, wv, wo -> out (B,T,E) fp32
// ---------------------------------------------------------------------------
extern "C" void kernel_launch(void* const* d_in, const int* in_sizes, int n_in,
                              void* d_out, int out_size)
{
    const float* x  = (const float*)d_in[0];
    // d_in[1] = causal mask (unused: causality computed directly)
    const float* wq = (const float*)d_in[2];
    const float* wk = (const float*)d_in[3];
    const float* wv = (const float*)d_in[4];
    const float* wo = (const float*)d_in[5];
    float* out = (float*)d_out;

    float *Qp, *Kp, *Vp, *AOp;
    cudaGetSymbolAddress((void**)&Qp,  g_Q);
    cudaGetSymbolAddress((void**)&Kp,  g_K);
    cudaGetSymbolAddress((void**)&Vp,  g_V);
    cudaGetSymbolAddress((void**)&AOp, g_AO);

    // QKV projections (tf32 tensor cores)
    {
        dim3 grid(QW / 128, ROWS / 128);
        gemm_tf32<<<grid, 256>>>(x, wq, Qp, ROWS, QW, E_DIM);
    }
    {
        dim3 grid(KW / 128, ROWS / 128);
        gemm_tf32<<<grid, 256>>>(x, wk, Kp, ROWS, KW, E_DIM);
        gemm_tf32<<<grid, 256>>>(x, wv, Vp, ROWS, KW, E_DIM);
    }

    // RoPE
    {
        int n = T_SEQ * (HD / 2);
        rope_table_kernel<<<(n + 255) / 256, 256>>>();
        int nq = ROWS * NH * (HD / 2);
        rope_apply_kernel<<<(nq + 255) / 256, 256>>>(Qp, NH);
        int nk = ROWS * NKV * (HD / 2);
        rope_apply_kernel<<<(nk + 255) / 256, 256>>>(Kp, NKV);
    }

    // Attention
    {
        dim3 grid(T_SEQ / 32, B_SZ * NH);
        attn_kernel<<<grid, 256>>>();
    }

    // Output projection (tf32 tensor cores)
    {
        dim3 grid(E_DIM / 128, ROWS / 128);
        gemm_tf32<<<grid, 256>>>(AOp, wo, out, ROWS, E_DIM, E_DIM);
    }
}

// round 7
// speedup vs baseline: 1.1912x; 1.0515x over previous
#include <cuda_runtime.h>
#include <math.h>
#include <stdint.h>

// Problem constants
#define B_SZ   2
#define T_SEQ  2048
#define E_DIM  2048
#define NH     16
#define NKV    8
#define HD     128
#define ROWS   (B_SZ * T_SEQ)        // 4096
#define QW     (NH * HD)             // 2048
#define KW     (NKV * HD)            // 1024

// Scratch (static device globals; no dynamic allocation allowed)
__device__ float g_Q[(size_t)ROWS * QW];     // 32 MB
__device__ float g_K[(size_t)ROWS * KW];     // 16 MB
__device__ float g_V[(size_t)ROWS * KW];     // 16 MB
__device__ float g_AO[(size_t)ROWS * QW];    // 32 MB
__device__ float g_WT[(size_t)E_DIM * E_DIM];// 16 MB (transposed tf32 weight, reused)
__device__ float g_cos[T_SEQ * (HD / 2)];
__device__ float g_sin[T_SEQ * (HD / 2)];

// ---------------------------------------------------------------------------
// Helpers
// ---------------------------------------------------------------------------
__device__ __forceinline__ float to_tf32(float x) {
    uint32_t u;
    asm("cvt.rna.tf32.f32 %0, %1;" : "=r"(u) : "f"(x));
    return __uint_as_float(u);
}

__device__ __forceinline__ void mma_tf32(float* d, const uint32_t* a, const uint32_t* b) {
    asm volatile(
        "mma.sync.aligned.m16n8k8.row.col.f32.tf32.tf32.f32 "
        "{%0,%1,%2,%3}, {%4,%5,%6,%7}, {%8,%9}, {%0,%1,%2,%3};\n"
        : "+f"(d[0]), "+f"(d[1]), "+f"(d[2]), "+f"(d[3])
        : "r"(a[0]), "r"(a[1]), "r"(a[2]), "r"(a[3]), "r"(b[0]), "r"(b[1]));
}

// ---------------------------------------------------------------------------
// TF32 mma.sync GEMM: C[M,N] = A[M,K] @ Bt[N,K]^T  (both K-major).
// A raw fp32 (rna-tf32 at staging); Bt pre-rounded to tf32.
// CTA 128x128, BK=32, 256 threads = 8 warps (2m x 4n), warp tile 64x32.
// Fragment-major ("quad") smem: each A fragment = 1 LDS.128; each B LDS.128
// feeds 2 n-tile fragments. Swizzle slot = lq*4 + (j ^ k8): conflict-free
// for both STS.128 staging and LDS.128 consumption.
// Requires M%128==0, N%128==0, K%32==0.
// ---------------------------------------------------------------------------
#define GBK 32
#define STG_BYTES 32768          // 16KB A + 16KB B per stage
#define GEMM_SMEM (2 * STG_BYTES)

__global__ __launch_bounds__(256) void gemm_mma(
    const float* __restrict__ A, const float* __restrict__ Bt,
    float* __restrict__ C, int M, int N, int K)
{
    extern __shared__ char smc[];
    const int tid = threadIdx.x;
    const int lane = tid & 31, warp = tid >> 5;
    const int lq = lane >> 2, s4 = lane & 3;
    const int wm = warp >> 2, wn = warp & 3;      // warp grid 2(m) x 4(n)
    const int m0 = blockIdx.y * 128, n0 = blockIdx.x * 128;

    // Staging role: thread -> (k8-chunk, 16-row group, row-in-group)
    const int sk8 = tid & 3;          // which k8 block (cols sk8*8..+7)
    const int slq = (tid >> 2) & 7;   // row lq within group
    const int sgrp = tid >> 5;        // 16-row group 0..7

    const float* Ag0 = A + (size_t)(m0 + sgrp * 16 + slq) * K + sk8 * 8;
    const float* Ag1 = Ag0 + (size_t)8 * K;
    const float* Bg0 = Bt + (size_t)(n0 + sgrp * 16 + slq) * K + sk8 * 8;
    const float* Bg1 = Bg0 + (size_t)8 * K;

    const int sts_base = (sk8 * 8 + sgrp) * 32;   // float4 index base

    float ar0[8], ar1[8], br0[8], br1[8];

    auto LDGALL = [&](int kt) {
        const float* a0 = Ag0 + kt * GBK;
        const float* a1 = Ag1 + kt * GBK;
        const float* b0 = Bg0 + kt * GBK;
        const float* b1 = Bg1 + kt * GBK;
        *(float4*)(ar0)     = *(const float4*)(a0);
        *(float4*)(ar0 + 4) = *(const float4*)(a0 + 4);
        *(float4*)(ar1)     = *(const float4*)(a1);
        *(float4*)(ar1 + 4) = *(const float4*)(a1 + 4);
        *(float4*)(br0)     = *(const float4*)(b0);
        *(float4*)(br0 + 4) = *(const float4*)(b0 + 4);
        *(float4*)(br1)     = *(const float4*)(b1);
        *(float4*)(br1 + 4) = *(const float4*)(b1 + 4);
    };
    auto STSALL = [&](int st) {
        float4* As = (float4*)(smc + st * STG_BYTES);
        float4* Bs = (float4*)(smc + st * STG_BYTES + 16384);
#pragma unroll
        for (int j = 0; j < 4; j++) {
            const int slot = slq * 4 + (j ^ sk8);
            As[sts_base + slot] = make_float4(to_tf32(ar0[j]), to_tf32(ar1[j]),
                                              to_tf32(ar0[j + 4]), to_tf32(ar1[j + 4]));
            Bs[sts_base + slot] = make_float4(br0[j], br1[j], br0[j + 4], br1[j + 4]);
        }
    };

    float acc[4][4][4];
#pragma unroll
    for (int mi = 0; mi < 4; mi++)
#pragma unroll
        for (int ni = 0; ni < 4; ni++)
#pragma unroll
            for (int j = 0; j < 4; j++) acc[mi][ni][j] = 0.f;

    const int nk = K / GBK;

    LDGALL(0);
    STSALL(0);
    __syncthreads();

    for (int kt = 0; kt < nk; kt++) {
        if (kt + 1 < nk) LDGALL(kt + 1);

        const float4* As = (const float4*)(smc + (kt & 1) * STG_BYTES);
        const float4* Bs = (const float4*)(smc + (kt & 1) * STG_BYTES + 16384);

#pragma unroll
        for (int k8 = 0; k8 < 4; k8++) {
            const int cslot = lq * 4 + (s4 ^ k8);
            uint32_t af[4][4], bf[4][2];
#pragma unroll
            for (int mi = 0; mi < 4; mi++) {
                float4 q = As[(k8 * 8 + wm * 4 + mi) * 32 + cslot];
                af[mi][0] = __float_as_uint(q.x); af[mi][1] = __float_as_uint(q.y);
                af[mi][2] = __float_as_uint(q.z); af[mi][3] = __float_as_uint(q.w);
            }
#pragma unroll
            for (int g = 0; g < 2; g++) {
                float4 q = Bs[(k8 * 8 + wn * 2 + g) * 32 + cslot];
                bf[g * 2 + 0][0] = __float_as_uint(q.x); bf[g * 2 + 0][1] = __float_as_uint(q.z);
                bf[g * 2 + 1][0] = __float_as_uint(q.y); bf[g * 2 + 1][1] = __float_as_uint(q.w);
            }
#pragma unroll
            for (int mi = 0; mi < 4; mi++)
#pragma unroll
                for (int ni = 0; ni < 4; ni++)
                    mma_tf32(acc[mi][ni], af[mi], bf[ni]);
        }

        if (kt + 1 < nk) {
            STSALL((kt + 1) & 1);
            __syncthreads();
        }
    }

    // Epilogue: c0,c1 = (row g, col t*2, t*2+1); c2,c3 = (row g+8, same cols)
#pragma unroll
    for (int mi = 0; mi < 4; mi++) {
        const int r0 = m0 + wm * 64 + mi * 16 + lq;
#pragma unroll
        for (int ni = 0; ni < 4; ni++) {
            const int c = n0 + wn * 32 + ni * 8 + s4 * 2;
            *(float2*)(C + (size_t)r0 * N + c)       = make_float2(acc[mi][ni][0], acc[mi][ni][1]);
            *(float2*)(C + (size_t)(r0 + 8) * N + c) = make_float2(acc[mi][ni][2], acc[mi][ni][3]);
        }
    }
}

// ---------------------------------------------------------------------------
// Transpose + tf32 rounding: out[C][R] = rna_tf32(in[R][C])^T
// Block (32,8), grid (C/32, R/32).
// ---------------------------------------------------------------------------
__global__ void transpose_round_kernel(const float* __restrict__ in, float* __restrict__ out,
                                       int R, int C)
{
    __shared__ float t[32][33];
    const int bx = blockIdx.x * 32, by = blockIdx.y * 32;
    const int tx = threadIdx.x, ty = threadIdx.y;
#pragma unroll
    for (int i = 0; i < 32; i += 8)
        t[ty + i][tx] = to_tf32(in[(size_t)(by + ty + i) * C + bx + tx]);
    __syncthreads();
#pragma unroll
    for (int i = 0; i < 32; i += 8)
        out[(size_t)(bx + ty + i) * R + by + tx] = t[tx][ty + i];
}

// ---------------------------------------------------------------------------
// RoPE table: cos/sin in double precision
// ---------------------------------------------------------------------------
__global__ void rope_table_kernel()
{
    int idx = blockIdx.x * blockDim.x + threadIdx.x;
    if (idx >= T_SEQ * (HD / 2)) return;
    int t = idx / (HD / 2);
    int i = idx % (HD / 2);
    double inv = pow(10000.0, -(double)(2 * i) / (double)HD);
    double ang = (double)t * inv;
    double s, c;
    sincos(ang, &s, &c);
    g_cos[idx] = (float)c;
    g_sin[idx] = (float)s;
}

// Apply RoPE in-place to tensor with layout (B*T, nheads*128)
__global__ void rope_apply_kernel(float* __restrict__ x, int nheads)
{
    int idx = blockIdx.x * blockDim.x + threadIdx.x;
    int pairs_per_row = nheads * (HD / 2);
    if (idx >= ROWS * pairs_per_row) return;
    int row = idx / pairs_per_row;
    int p = idx - row * pairs_per_row;
    int h = p / (HD / 2);
    int i = p - h * (HD / 2);
    int t = row & (T_SEQ - 1);
    float c = g_cos[t * (HD / 2) + i];
    float s = g_sin[t * (HD / 2) + i];
    float* base = x + (size_t)row * nheads * HD + h * HD + 2 * i;
    float x0 = base[0], x1 = base[1];
    base[0] = x0 * c - x1 * s;
    base[1] = x0 * s + x1 * c;
}

// ---------------------------------------------------------------------------
// Flash attention, fp32, causal, GQA (2 q heads per kv head). (unchanged)
// ---------------------------------------------------------------------------
__global__ __launch_bounds__(256) void attn_kernel()
{
    __shared__ float Ks[32 * 128];
    __shared__ float Vs[32 * 128];

    const int tid = threadIdx.x;
    const int w = tid >> 5, lane = tid & 31;
    const int rl = (w << 2) + (lane >> 3);   // local q row 0..31
    const int g = lane & 7;                  // 16-dim group 0..7

    const int qb = blockIdx.x;               // q tile index
    const int bh = blockIdx.y;
    const int b = bh >> 4, h = bh & 15;
    const int kh = h >> 1;                   // GQA: kv head
    const int qi = qb * 32 + rl;

    const float scale = 0.08838834764831845f;  // 128^-0.5

    float q[16], o[16];
    const float* qptr = g_Q + (size_t)(b * T_SEQ + qi) * QW + h * HD + g * 16;
#pragma unroll
    for (int j = 0; j < 16; j++) { q[j] = qptr[j] * scale; o[j] = 0.f; }

    float m = -INFINITY, l = 0.f;

    for (int t0 = 0; t0 <= qb; t0++) {
        const int k0 = t0 * 32;
        const float* Kb = g_K + (size_t)(b * T_SEQ + k0) * KW + kh * HD;
        const float* Vb = g_V + (size_t)(b * T_SEQ + k0) * KW + kh * HD;

        __syncthreads();
#pragma unroll
        for (int it = 0; it < 4; it++) {
            int idx = tid + it * 256;        // float4 index 0..1023
            int r = idx >> 5;
            int c = idx & 31;
            ((float4*)Ks)[idx] = *(const float4*)(Kb + (size_t)r * KW + c * 4);
            ((float4*)Vs)[idx] = *(const float4*)(Vb + (size_t)r * KW + c * 4);
        }
        __syncthreads();

        const bool diag = (t0 == qb);
        float sreg[4];
        float tmax = -INFINITY;

#pragma unroll
        for (int kk = 0; kk < 32; kk++) {
            const float4* kr = (const float4*)(Ks + kk * 128 + g * 16);
            float4 ka = kr[0], kb2 = kr[1], kc = kr[2], kd = kr[3];
            float s;
            s = q[0] * ka.x;
            s = fmaf(q[1],  ka.y,  s); s = fmaf(q[2],  ka.z,  s); s = fmaf(q[3],  ka.w,  s);
            s = fmaf(q[4],  kb2.x, s); s = fmaf(q[5],  kb2.y, s); s = fmaf(q[6],  kb2.z, s); s = fmaf(q[7],  kb2.w, s);
            s = fmaf(q[8],  kc.x,  s); s = fmaf(q[9],  kc.y,  s); s = fmaf(q[10], kc.z,  s); s = fmaf(q[11], kc.w,  s);
            s = fmaf(q[12], kd.x,  s); s = fmaf(q[13], kd.y,  s); s = fmaf(q[14], kd.z,  s); s = fmaf(q[15], kd.w,  s);
            s += __shfl_xor_sync(0xffffffffu, s, 1);
            s += __shfl_xor_sync(0xffffffffu, s, 2);
            s += __shfl_xor_sync(0xffffffffu, s, 4);
            if (diag && (k0 + kk > qi)) s = -INFINITY;
            if ((kk & 7) == g) sreg[kk >> 3] = s;
            tmax = fmaxf(tmax, s);
        }

        float mnew = fmaxf(m, tmax);
        float corr = __expf(m - mnew);
        l *= corr;
#pragma unroll
        for (int j = 0; j < 16; j++) o[j] *= corr;
        m = mnew;

#pragma unroll
        for (int kk = 0; kk < 32; kk++) {
            float s = __shfl_sync(0xffffffffu, sreg[kk >> 3], kk & 7, 8);
            float p = __expf(s - m);
            l += p;
            const float4* vr = (const float4*)(Vs + kk * 128 + g * 16);
            float4 va = vr[0], vb2 = vr[1], vc = vr[2], vd = vr[3];
            o[0]  = fmaf(p, va.x,  o[0]);  o[1]  = fmaf(p, va.y,  o[1]);
            o[2]  = fmaf(p, va.z,  o[2]);  o[3]  = fmaf(p, va.w,  o[3]);
            o[4]  = fmaf(p, vb2.x, o[4]);  o[5]  = fmaf(p, vb2.y, o[5]);
            o[6]  = fmaf(p, vb2.z, o[6]);  o[7]  = fmaf(p, vb2.w, o[7]);
            o[8]  = fmaf(p, vc.x,  o[8]);  o[9]  = fmaf(p, vc.y,  o[9]);
            o[10] = fmaf(p, vc.z,  o[10]); o[11] = fmaf(p, vc.w,  o[11]);
            o[12] = fmaf(p, vd.x,  o[12]); o[13] = fmaf(p, vd.y,  o[13]);
            o[14] = fmaf(p, vd.z,  o[14]); o[15] = fmaf(p, vd.w,  o[15]);
        }
    }

    const float inv = 1.f / l;
    float* outp = g_AO + (size_t)(b * T_SEQ + qi) * QW + h * HD + g * 16;
#pragma unroll
    for (int v4 = 0; v4 < 4; v4++) {
        float4 ov = make_float4(o[v4 * 4 + 0] * inv, o[v4 * 4 + 1] * inv,
                                o[v4 * 4 + 2] * inv, o[v4 * 4 + 3] * inv);
        *(float4*)(outp + v4 * 4) = ov;
    }
}

// ---------------------------------------------------------------------------
// kernel_launch: x, mask, wq, wk, wv, wo -> out (B,T,E) fp32
// ---------------------------------------------------------------------------
extern "C" void kernel_launch(void* const* d_in, const int* in_sizes, int n_in,
                              void* d_out, int out_size)
{
    const float* x  = (const float*)d_in[0];
    // d_in[1] = causal mask (unused: causality computed directly)
    const float* wq = (const float*)d_in[2];
    const float* wk = (const float*)d_in[3];
    const float* wv = (const float*)d_in[4];
    const float* wo = (const float*)d_in[5];
    float* out = (float*)d_out;

    float *Qp, *Kp, *Vp, *AOp, *WTp;
    cudaGetSymbolAddress((void**)&Qp,  g_Q);
    cudaGetSymbolAddress((void**)&Kp,  g_K);
    cudaGetSymbolAddress((void**)&Vp,  g_V);
    cudaGetSymbolAddress((void**)&AOp, g_AO);
    cudaGetSymbolAddress((void**)&WTp, g_WT);

    cudaFuncSetAttribute(gemm_mma, cudaFuncAttributeMaxDynamicSharedMemorySize, GEMM_SMEM);

    // Q = X @ Wq
    {
        dim3 tg(E_DIM / 32, E_DIM / 32);
        transpose_round_kernel<<<tg, dim3(32, 8)>>>(wq, WTp, E_DIM, QW);
        dim3 grid(QW / 128, ROWS / 128);
        gemm_mma<<<grid, 256, GEMM_SMEM>>>(x, WTp, Qp, ROWS, QW, E_DIM);
    }
    // K = X @ Wk
    {
        dim3 tg(KW / 32, E_DIM / 32);
        transpose_round_kernel<<<tg, dim3(32, 8)>>>(wk, WTp, E_DIM, KW);
        dim3 grid(KW / 128, ROWS / 128);
        gemm_mma<<<grid, 256, GEMM_SMEM>>>(x, WTp, Kp, ROWS, KW, E_DIM);
    }
    // V = X @ Wv
    {
        dim3 tg(KW / 32, E_DIM / 32);
        transpose_round_kernel<<<tg, dim3(32, 8)>>>(wv, WTp, E_DIM, KW);
        dim3 grid(KW / 128, ROWS / 128);
        gemm_mma<<<grid, 256, GEMM_SMEM>>>(x, WTp, Vp, ROWS, KW, E_DIM);
    }

    // RoPE
    {
        int n = T_SEQ * (HD / 2);
        rope_table_kernel<<<(n + 255) / 256, 256>>>();
        int nq = ROWS * NH * (HD / 2);
        rope_apply_kernel<<<(nq + 255) / 256, 256>>>(Qp, NH);
        int nk = ROWS * NKV * (HD / 2);
        rope_apply_kernel<<<(nk + 255) / 256, 256>>>(Kp, NKV);
    }

    // Attention
    {
        dim3 grid(T_SEQ / 32, B_SZ * NH);
        attn_kernel<<<grid, 256>>>();
    }

    // out = AO @ Wo
    {
        dim3 tg(E_DIM / 32, QW / 32);
        transpose_round_kernel<<<tg, dim3(32, 8)>>>(wo, WTp, QW, E_DIM);
        dim3 grid(E_DIM / 128, ROWS / 128);
        gemm_mma<<<grid, 256, GEMM_SMEM>>>(AOp, WTp, out, ROWS, E_DIM, E_DIM);
    }
}

// round 8
// speedup vs baseline: 1.2025x; 1.0095x over previous
#include <cuda_runtime.h>
#include <math.h>
#include <stdint.h>

// Problem constants
#define B_SZ   2
#define T_SEQ  2048
#define E_DIM  2048
#define NH     16
#define NKV    8
#define HD     128
#define ROWS   (B_SZ * T_SEQ)        // 4096
#define QW     (NH * HD)             // 2048
#define KW     (NKV * HD)            // 1024

// Scratch (static device globals; no dynamic allocation allowed)
__device__ float g_Q[(size_t)ROWS * QW];     // 32 MB
__device__ float g_K[(size_t)ROWS * KW];     // 16 MB
__device__ float g_V[(size_t)ROWS * KW];     // 16 MB
__device__ float g_AO[(size_t)ROWS * QW];    // 32 MB
__device__ float g_WT[(size_t)E_DIM * E_DIM];// 16 MB (transposed tf32 weight, reused)
__device__ float g_cos[T_SEQ * (HD / 2)];
__device__ float g_sin[T_SEQ * (HD / 2)];

// ---------------------------------------------------------------------------
// Helpers
// ---------------------------------------------------------------------------
__device__ __forceinline__ float to_tf32(float x) {
    uint32_t u;
    asm("cvt.rna.tf32.f32 %0, %1;" : "=r"(u) : "f"(x));
    return __uint_as_float(u);
}

__device__ __forceinline__ void mma_tf32(float* d, const uint32_t* a, const uint32_t* b) {
    asm volatile(
        "mma.sync.aligned.m16n8k8.row.col.f32.tf32.tf32.f32 "
        "{%0,%1,%2,%3}, {%4,%5,%6,%7}, {%8,%9}, {%0,%1,%2,%3};\n"
        : "+f"(d[0]), "+f"(d[1]), "+f"(d[2]), "+f"(d[3])
        : "r"(a[0]), "r"(a[1]), "r"(a[2]), "r"(a[3]), "r"(b[0]), "r"(b[1]));
}

// ---------------------------------------------------------------------------
// TF32 mma.sync GEMM: C[M,N] = A[M,K] @ Bt[N,K]^T  (both K-major).
// A raw fp32 (rna-tf32 at staging); Bt pre-rounded to tf32.
// CTA 128x128, BK=32, 256 threads = 8 warps (2m x 4n), warp tile 64x32.
// Fragment-major ("quad") smem: each A fragment = 1 LDS.128; each B LDS.128
// feeds 2 n-tile fragments. Swizzle slot = lq*4 + (j ^ k8): conflict-free
// for both STS.128 staging and LDS.128 consumption.
// Requires M%128==0, N%128==0, K%32==0.
// ---------------------------------------------------------------------------
#define GBK 32
#define STG_BYTES 32768          // 16KB A + 16KB B per stage
#define GEMM_SMEM (2 * STG_BYTES)

__global__ __launch_bounds__(256) void gemm_mma(
    const float* __restrict__ A, const float* __restrict__ Bt,
    float* __restrict__ C, int M, int N, int K)
{
    extern __shared__ char smc[];
    const int tid = threadIdx.x;
    const int lane = tid & 31, warp = tid >> 5;
    const int lq = lane >> 2, s4 = lane & 3;
    const int wm = warp >> 2, wn = warp & 3;      // warp grid 2(m) x 4(n)
    const int m0 = blockIdx.y * 128, n0 = blockIdx.x * 128;

    // Staging role: thread -> (k8-chunk, 16-row group, row-in-group)
    const int sk8 = tid & 3;          // which k8 block (cols sk8*8..+7)
    const int slq = (tid >> 2) & 7;   // row lq within group
    const int sgrp = tid >> 5;        // 16-row group 0..7

    const float* Ag0 = A + (size_t)(m0 + sgrp * 16 + slq) * K + sk8 * 8;
    const float* Ag1 = Ag0 + (size_t)8 * K;
    const float* Bg0 = Bt + (size_t)(n0 + sgrp * 16 + slq) * K + sk8 * 8;
    const float* Bg1 = Bg0 + (size_t)8 * K;

    const int sts_base = (sk8 * 8 + sgrp) * 32;   // float4 index base

    float ar0[8], ar1[8], br0[8], br1[8];

    auto LDGALL = [&](int kt) {
        const float* a0 = Ag0 + kt * GBK;
        const float* a1 = Ag1 + kt * GBK;
        const float* b0 = Bg0 + kt * GBK;
        const float* b1 = Bg1 + kt * GBK;
        *(float4*)(ar0)     = *(const float4*)(a0);
        *(float4*)(ar0 + 4) = *(const float4*)(a0 + 4);
        *(float4*)(ar1)     = *(const float4*)(a1);
        *(float4*)(ar1 + 4) = *(const float4*)(a1 + 4);
        *(float4*)(br0)     = *(const float4*)(b0);
        *(float4*)(br0 + 4) = *(const float4*)(b0 + 4);
        *(float4*)(br1)     = *(const float4*)(b1);
        *(float4*)(br1 + 4) = *(const float4*)(b1 + 4);
    };
    auto STSALL = [&](int st) {
        float4* As = (float4*)(smc + st * STG_BYTES);
        float4* Bs = (float4*)(smc + st * STG_BYTES + 16384);
#pragma unroll
        for (int j = 0; j < 4; j++) {
            const int slot = slq * 4 + (j ^ sk8);
            As[sts_base + slot] = make_float4(to_tf32(ar0[j]), to_tf32(ar1[j]),
                                              to_tf32(ar0[j + 4]), to_tf32(ar1[j + 4]));
            Bs[sts_base + slot] = make_float4(br0[j], br1[j], br0[j + 4], br1[j + 4]);
        }
    };

    float acc[4][4][4];
#pragma unroll
    for (int mi = 0; mi < 4; mi++)
#pragma unroll
        for (int ni = 0; ni < 4; ni++)
#pragma unroll
            for (int j = 0; j < 4; j++) acc[mi][ni][j] = 0.f;

    const int nk = K / GBK;

    LDGALL(0);
    STSALL(0);
    __syncthreads();

    for (int kt = 0; kt < nk; kt++) {
        if (kt + 1 < nk) LDGALL(kt + 1);

        const float4* As = (const float4*)(smc + (kt & 1) * STG_BYTES);
        const float4* Bs = (const float4*)(smc + (kt & 1) * STG_BYTES + 16384);

#pragma unroll
        for (int k8 = 0; k8 < 4; k8++) {
            const int cslot = lq * 4 + (s4 ^ k8);
            uint32_t af[4][4], bf[4][2];
#pragma unroll
            for (int mi = 0; mi < 4; mi++) {
                float4 q = As[(k8 * 8 + wm * 4 + mi) * 32 + cslot];
                af[mi][0] = __float_as_uint(q.x); af[mi][1] = __float_as_uint(q.y);
                af[mi][2] = __float_as_uint(q.z); af[mi][3] = __float_as_uint(q.w);
            }
#pragma unroll
            for (int g = 0; g < 2; g++) {
                float4 q = Bs[(k8 * 8 + wn * 2 + g) * 32 + cslot];
                bf[g * 2 + 0][0] = __float_as_uint(q.x); bf[g * 2 + 0][1] = __float_as_uint(q.z);
                bf[g * 2 + 1][0] = __float_as_uint(q.y); bf[g * 2 + 1][1] = __float_as_uint(q.w);
            }
#pragma unroll
            for (int mi = 0; mi < 4; mi++)
#pragma unroll
                for (int ni = 0; ni < 4; ni++)
                    mma_tf32(acc[mi][ni], af[mi], bf[ni]);
        }

        if (kt + 1 < nk) {
            STSALL((kt + 1) & 1);
            __syncthreads();
        }
    }

    // Epilogue: c0,c1 = (row g, col t*2, t*2+1); c2,c3 = (row g+8, same cols)
#pragma unroll
    for (int mi = 0; mi < 4; mi++) {
        const int r0 = m0 + wm * 64 + mi * 16 + lq;
#pragma unroll
        for (int ni = 0; ni < 4; ni++) {
            const int c = n0 + wn * 32 + ni * 8 + s4 * 2;
            *(float2*)(C + (size_t)r0 * N + c)       = make_float2(acc[mi][ni][0], acc[mi][ni][1]);
            *(float2*)(C + (size_t)(r0 + 8) * N + c) = make_float2(acc[mi][ni][2], acc[mi][ni][3]);
        }
    }
}

// ---------------------------------------------------------------------------
// Transpose + tf32 rounding: out[C][R] = rna_tf32(in[R][C])^T
// Block (32,8), grid (C/32, R/32).
// ---------------------------------------------------------------------------
__global__ void transpose_round_kernel(const float* __restrict__ in, float* __restrict__ out,
                                       int R, int C)
{
    __shared__ float t[32][33];
    const int bx = blockIdx.x * 32, by = blockIdx.y * 32;
    const int tx = threadIdx.x, ty = threadIdx.y;
#pragma unroll
    for (int i = 0; i < 32; i += 8)
        t[ty + i][tx] = to_tf32(in[(size_t)(by + ty + i) * C + bx + tx]);
    __syncthreads();
#pragma unroll
    for (int i = 0; i < 32; i += 8)
        out[(size_t)(bx + ty + i) * R + by + tx] = t[tx][ty + i];
}

// ---------------------------------------------------------------------------
// RoPE table: cos/sin in double precision
// ---------------------------------------------------------------------------
__global__ void rope_table_kernel()
{
    int idx = blockIdx.x * blockDim.x + threadIdx.x;
    if (idx >= T_SEQ * (HD / 2)) return;
    int t = idx / (HD / 2);
    int i = idx % (HD / 2);
    double inv = pow(10000.0, -(double)(2 * i) / (double)HD);
    double ang = (double)t * inv;
    double s, c;
    sincos(ang, &s, &c);
    g_cos[idx] = (float)c;
    g_sin[idx] = (float)s;
}

// Apply RoPE in-place to tensor with layout (B*T, nheads*128)
__global__ void rope_apply_kernel(float* __restrict__ x, int nheads)
{
    int idx = blockIdx.x * blockDim.x + threadIdx.x;
    int pairs_per_row = nheads * (HD / 2);
    if (idx >= ROWS * pairs_per_row) return;
    int row = idx / pairs_per_row;
    int p = idx - row * pairs_per_row;
    int h = p / (HD / 2);
    int i = p - h * (HD / 2);
    int t = row & (T_SEQ - 1);
    float c = g_cos[t * (HD / 2) + i];
    float s = g_sin[t * (HD / 2) + i];
    float* base = x + (size_t)row * nheads * HD + h * HD + 2 * i;
    float x0 = base[0], x1 = base[1];
    base[0] = x0 * c - x1 * s;
    base[1] = x0 * s + x1 * c;
}

// ---------------------------------------------------------------------------
// Flash attention, fp32, causal, GQA (2 q heads per kv head). (unchanged)
// ---------------------------------------------------------------------------
__global__ __launch_bounds__(256) void attn_kernel()
{
    __shared__ float Ks[32 * 128];
    __shared__ float Vs[32 * 128];

    const int tid = threadIdx.x;
    const int w = tid >> 5, lane = tid & 31;
    const int rl = (w << 2) + (lane >> 3);   // local q row 0..31
    const int g = lane & 7;                  // 16-dim group 0..7

    const int qb = blockIdx.x;               // q tile index
    const int bh = blockIdx.y;
    const int b = bh >> 4, h = bh & 15;
    const int kh = h >> 1;                   // GQA: kv head
    const int qi = qb * 32 + rl;

    const float scale = 0.08838834764831845f;  // 128^-0.5

    float q[16], o[16];
    const float* qptr = g_Q + (size_t)(b * T_SEQ + qi) * QW + h * HD + g * 16;
#pragma unroll
    for (int j = 0; j < 16; j++) { q[j] = qptr[j] * scale; o[j] = 0.f; }

    float m = -INFINITY, l = 0.f;

    for (int t0 = 0; t0 <= qb; t0++) {
        const int k0 = t0 * 32;
        const float* Kb = g_K + (size_t)(b * T_SEQ + k0) * KW + kh * HD;
        const float* Vb = g_V + (size_t)(b * T_SEQ + k0) * KW + kh * HD;

        __syncthreads();
#pragma unroll
        for (int it = 0; it < 4; it++) {
            int idx = tid + it * 256;        // float4 index 0..1023
            int r = idx >> 5;
            int c = idx & 31;
            ((float4*)Ks)[idx] = *(const float4*)(Kb + (size_t)r * KW + c * 4);
            ((float4*)Vs)[idx] = *(const float4*)(Vb + (size_t)r * KW + c * 4);
        }
        __syncthreads();

        const bool diag = (t0 == qb);
        float sreg[4];
        float tmax = -INFINITY;

#pragma unroll
        for (int kk = 0; kk < 32; kk++) {
            const float4* kr = (const float4*)(Ks + kk * 128 + g * 16);
            float4 ka = kr[0], kb2 = kr[1], kc = kr[2], kd = kr[3];
            float s;
            s = q[0] * ka.x;
            s = fmaf(q[1],  ka.y,  s); s = fmaf(q[2],  ka.z,  s); s = fmaf(q[3],  ka.w,  s);
            s = fmaf(q[4],  kb2.x, s); s = fmaf(q[5],  kb2.y, s); s = fmaf(q[6],  kb2.z, s); s = fmaf(q[7],  kb2.w, s);
            s = fmaf(q[8],  kc.x,  s); s = fmaf(q[9],  kc.y,  s); s = fmaf(q[10], kc.z,  s); s = fmaf(q[11], kc.w,  s);
            s = fmaf(q[12], kd.x,  s); s = fmaf(q[13], kd.y,  s); s = fmaf(q[14], kd.z,  s); s = fmaf(q[15], kd.w,  s);
            s += __shfl_xor_sync(0xffffffffu, s, 1);
            s += __shfl_xor_sync(0xffffffffu, s, 2);
            s += __shfl_xor_sync(0xffffffffu, s, 4);
            if (diag && (k0 + kk > qi)) s = -INFINITY;
            if ((kk & 7) == g) sreg[kk >> 3] = s;
            tmax = fmaxf(tmax, s);
        }

        float mnew = fmaxf(m, tmax);
        float corr = __expf(m - mnew);
        l *= corr;
#pragma unroll
        for (int j = 0; j < 16; j++) o[j] *= corr;
        m = mnew;

#pragma unroll
        for (int kk = 0; kk < 32; kk++) {
            float s = __shfl_sync(0xffffffffu, sreg[kk >> 3], kk & 7, 8);
            float p = __expf(s - m);
            l += p;
            const float4* vr = (const float4*)(Vs + kk * 128 + g * 16);
            float4 va = vr[0], vb2 = vr[1], vc = vr[2], vd = vr[3];
            o[0]  = fmaf(p, va.x,  o[0]);  o[1]  = fmaf(p, va.y,  o[1]);
            o[2]  = fmaf(p, va.z,  o[2]);  o[3]  = fmaf(p, va.w,  o[3]);
            o[4]  = fmaf(p, vb2.x, o[4]);  o[5]  = fmaf(p, vb2.y, o[5]);
            o[6]  = fmaf(p, vb2.z, o[6]);  o[7]  = fmaf(p, vb2.w, o[7]);
            o[8]  = fmaf(p, vc.x,  o[8]);  o[9]  = fmaf(p, vc.y,  o[9]);
            o[10] = fmaf(p, vc.z,  o[10]); o[11] = fmaf(p, vc.w,  o[11]);
            o[12] = fmaf(p, vd.x,  o[12]); o[13] = fmaf(p, vd.y,  o[13]);
            o[14] = fmaf(p, vd.z,  o[14]); o[15] = fmaf(p, vd.w,  o[15]);
        }
    }

    const float inv = 1.f / l;
    float* outp = g_AO + (size_t)(b * T_SEQ + qi) * QW + h * HD + g * 16;
#pragma unroll
    for (int v4 = 0; v4 < 4; v4++) {
        float4 ov = make_float4(o[v4 * 4 + 0] * inv, o[v4 * 4 + 1] * inv,
                                o[v4 * 4 + 2] * inv, o[v4 * 4 + 3] * inv);
        *(float4*)(outp + v4 * 4) = ov;
    }
}

// ---------------------------------------------------------------------------
// kernel_launch: x, mask, wq, wk, wv, wo -> out (B,T,E) fp32
// ---------------------------------------------------------------------------
extern "C" void kernel_launch(void* const* d_in, const int* in_sizes, int n_in,
                              void* d_out, int out_size)
{
    const float* x  = (const float*)d_in[0];
    // d_in[1] = causal mask (unused: causality computed directly)
    const float* wq = (const float*)d_in[2];
    const float* wk = (const float*)d_in[3];
    const float* wv = (const float*)d_in[4];
    const float* wo = (const float*)d_in[5];
    float* out = (float*)d_out;

    float *Qp, *Kp, *Vp, *AOp, *WTp;
    cudaGetSymbolAddress((void**)&Qp,  g_Q);
    cudaGetSymbolAddress((void**)&Kp,  g_K);
    cudaGetSymbolAddress((void**)&Vp,  g_V);
    cudaGetSymbolAddress((void**)&AOp, g_AO);
    cudaGetSymbolAddress((void**)&WTp, g_WT);

    cudaFuncSetAttribute(gemm_mma, cudaFuncAttributeMaxDynamicSharedMemorySize, GEMM_SMEM);

    // Q = X @ Wq
    {
        dim3 tg(E_DIM / 32, E_DIM / 32);
        transpose_round_kernel<<<tg, dim3(32, 8)>>>(wq, WTp, E_DIM, QW);
        dim3 grid(QW / 128, ROWS / 128);
        gemm_mma<<<grid, 256, GEMM_SMEM>>>(x, WTp, Qp, ROWS, QW, E_DIM);
    }
    // K = X @ Wk
    {
        dim3 tg(KW / 32, E_DIM / 32);
        transpose_round_kernel<<<tg, dim3(32, 8)>>>(wk, WTp, E_DIM, KW);
        dim3 grid(KW / 128, ROWS / 128);
        gemm_mma<<<grid, 256, GEMM_SMEM>>>(x, WTp, Kp, ROWS, KW, E_DIM);
    }
    // V = X @ Wv
    {
        dim3 tg(KW / 32, E_DIM / 32);
        transpose_round_kernel<<<tg, dim3(32, 8)>>>(wv, WTp, E_DIM, KW);
        dim3 grid(KW / 128, ROWS / 128);
        gemm_mma<<<grid, 256, GEMM_SMEM>>>(x, WTp, Vp, ROWS, KW, E_DIM);
    }

    // RoPE
    {
        int n = T_SEQ * (HD / 2);
        rope_table_kernel<<<(n + 255) / 256, 256>>>();
        int nq = ROWS * NH * (HD / 2);
        rope_apply_kernel<<<(nq + 255) / 256, 256>>>(Qp, NH);
        int nk = ROWS * NKV * (HD / 2);
        rope_apply_kernel<<<(nk + 255) / 256, 256>>>(Kp, NKV);
    }

    // Attention
    {
        dim3 grid(T_SEQ / 32, B_SZ * NH);
        attn_kernel<<<grid, 256>>>();
    }

    // out = AO @ Wo
    {
        dim3 tg(E_DIM / 32, QW / 32);
        transpose_round_kernel<<<tg, dim3(32, 8)>>>(wo, WTp, QW, E_DIM);
        dim3 grid(E_DIM / 128, ROWS / 128);
        gemm_mma<<<grid, 256, GEMM_SMEM>>>(AOp, WTp, out, ROWS, E_DIM, E_DIM);
    }
}

// round 9
// speedup vs baseline: 1.2038x; 1.0010x over previous
#include <cuda_runtime.h>
#include <math.h>
#include <stdint.h>

// Problem constants
#define B_SZ   2
#define T_SEQ  2048
#define E_DIM  2048
#define NH     16
#define NKV    8
#define HD     128
#define ROWS   (B_SZ * T_SEQ)        // 4096
#define QW     (NH * HD)             // 2048
#define KW     (NKV * HD)            // 1024

// Scratch (static device globals; no dynamic allocation allowed)
__device__ float g_Q[(size_t)ROWS * QW];     // 32 MB
__device__ float g_K[(size_t)ROWS * KW];     // 16 MB
__device__ float g_V[(size_t)ROWS * KW];     // 16 MB
__device__ float g_AO[(size_t)ROWS * QW];    // 32 MB
__device__ float g_WT[(size_t)E_DIM * E_DIM];// 16 MB (transposed tf32 weight, reused)
__device__ float g_cos[T_SEQ * (HD / 2)];
__device__ float g_sin[T_SEQ * (HD / 2)];

// ---------------------------------------------------------------------------
// Helpers
// ---------------------------------------------------------------------------
__device__ __forceinline__ float to_tf32(float x) {
    uint32_t u;
    asm("cvt.rna.tf32.f32 %0, %1;" : "=r"(u) : "f"(x));
    return __uint_as_float(u);
}

__device__ __forceinline__ void mma_tf32(float* d, const uint32_t* a, const uint32_t* b) {
    asm volatile(
        "mma.sync.aligned.m16n8k8.row.col.f32.tf32.tf32.f32 "
        "{%0,%1,%2,%3}, {%4,%5,%6,%7}, {%8,%9}, {%0,%1,%2,%3};\n"
        : "+f"(d[0]), "+f"(d[1]), "+f"(d[2]), "+f"(d[3])
        : "r"(a[0]), "r"(a[1]), "r"(a[2]), "r"(a[3]), "r"(b[0]), "r"(b[1]));
}

// ---------------------------------------------------------------------------
// TF32 mma.sync GEMM: C[M,N] = A[M,K] @ Bt[N,K]^T  (both K-major).
// A raw fp32 (rna-tf32 at staging); Bt pre-rounded to tf32.
// CTA 128x128, BK=32, 256 threads = 8 warps (2m x 4n), warp tile 64x32.
// Fragment-major ("quad") smem: each A fragment = 1 LDS.128; each B LDS.128
// feeds 2 n-tile fragments. Swizzle slot = lq*4 + (j ^ k8): conflict-free
// for both STS.128 staging and LDS.128 consumption.
// Requires M%128==0, N%128==0, K%32==0.
// ---------------------------------------------------------------------------
#define GBK 32
#define STG_BYTES 32768          // 16KB A + 16KB B per stage
#define GEMM_SMEM (2 * STG_BYTES)

__global__ __launch_bounds__(256) void gemm_mma(
    const float* __restrict__ A, const float* __restrict__ Bt,
    float* __restrict__ C, int M, int N, int K)
{
    extern __shared__ char smc[];
    const int tid = threadIdx.x;
    const int lane = tid & 31, warp = tid >> 5;
    const int lq = lane >> 2, s4 = lane & 3;
    const int wm = warp >> 2, wn = warp & 3;      // warp grid 2(m) x 4(n)
    const int m0 = blockIdx.y * 128, n0 = blockIdx.x * 128;

    // Staging role: thread -> (k8-chunk, 16-row group, row-in-group)
    const int sk8 = tid & 3;          // which k8 block (cols sk8*8..+7)
    const int slq = (tid >> 2) & 7;   // row lq within group
    const int sgrp = tid >> 5;        // 16-row group 0..7

    const float* Ag0 = A + (size_t)(m0 + sgrp * 16 + slq) * K + sk8 * 8;
    const float* Ag1 = Ag0 + (size_t)8 * K;
    const float* Bg0 = Bt + (size_t)(n0 + sgrp * 16 + slq) * K + sk8 * 8;
    const float* Bg1 = Bg0 + (size_t)8 * K;

    const int sts_base = (sk8 * 8 + sgrp) * 32;   // float4 index base

    float ar0[8], ar1[8], br0[8], br1[8];

    auto LDGALL = [&](int kt) {
        const float* a0 = Ag0 + kt * GBK;
        const float* a1 = Ag1 + kt * GBK;
        const float* b0 = Bg0 + kt * GBK;
        const float* b1 = Bg1 + kt * GBK;
        *(float4*)(ar0)     = *(const float4*)(a0);
        *(float4*)(ar0 + 4) = *(const float4*)(a0 + 4);
        *(float4*)(ar1)     = *(const float4*)(a1);
        *(float4*)(ar1 + 4) = *(const float4*)(a1 + 4);
        *(float4*)(br0)     = *(const float4*)(b0);
        *(float4*)(br0 + 4) = *(const float4*)(b0 + 4);
        *(float4*)(br1)     = *(const float4*)(b1);
        *(float4*)(br1 + 4) = *(const float4*)(b1 + 4);
    };
    auto STSALL = [&](int st) {
        float4* As = (float4*)(smc + st * STG_BYTES);
        float4* Bs = (float4*)(smc + st * STG_BYTES + 16384);
#pragma unroll
        for (int j = 0; j < 4; j++) {
            const int slot = slq * 4 + (j ^ sk8);
            As[sts_base + slot] = make_float4(to_tf32(ar0[j]), to_tf32(ar1[j]),
                                              to_tf32(ar0[j + 4]), to_tf32(ar1[j + 4]));
            Bs[sts_base + slot] = make_float4(br0[j], br1[j], br0[j + 4], br1[j + 4]);
        }
    };

    float acc[4][4][4];
#pragma unroll
    for (int mi = 0; mi < 4; mi++)
#pragma unroll
        for (int ni = 0; ni < 4; ni++)
#pragma unroll
            for (int j = 0; j < 4; j++) acc[mi][ni][j] = 0.f;

    const int nk = K / GBK;

    LDGALL(0);
    STSALL(0);
    __syncthreads();

    for (int kt = 0; kt < nk; kt++) {
        if (kt + 1 < nk) LDGALL(kt + 1);

        const float4* As = (const float4*)(smc + (kt & 1) * STG_BYTES);
        const float4* Bs = (const float4*)(smc + (kt & 1) * STG_BYTES + 16384);

#pragma unroll
        for (int k8 = 0; k8 < 4; k8++) {
            const int cslot = lq * 4 + (s4 ^ k8);
            uint32_t af[4][4], bf[4][2];
#pragma unroll
            for (int mi = 0; mi < 4; mi++) {
                float4 q = As[(k8 * 8 + wm * 4 + mi) * 32 + cslot];
                af[mi][0] = __float_as_uint(q.x); af[mi][1] = __float_as_uint(q.y);
                af[mi][2] = __float_as_uint(q.z); af[mi][3] = __float_as_uint(q.w);
            }
#pragma unroll
            for (int g = 0; g < 2; g++) {
                float4 q = Bs[(k8 * 8 + wn * 2 + g) * 32 + cslot];
                bf[g * 2 + 0][0] = __float_as_uint(q.x); bf[g * 2 + 0][1] = __float_as_uint(q.z);
                bf[g * 2 + 1][0] = __float_as_uint(q.y); bf[g * 2 + 1][1] = __float_as_uint(q.w);
            }
#pragma unroll
            for (int mi = 0; mi < 4; mi++)
#pragma unroll
                for (int ni = 0; ni < 4; ni++)
                    mma_tf32(acc[mi][ni], af[mi], bf[ni]);
        }

        if (kt + 1 < nk) {
            STSALL((kt + 1) & 1);
            __syncthreads();
        }
    }

    // Epilogue: c0,c1 = (row g, col t*2, t*2+1); c2,c3 = (row g+8, same cols)
#pragma unroll
    for (int mi = 0; mi < 4; mi++) {
        const int r0 = m0 + wm * 64 + mi * 16 + lq;
#pragma unroll
        for (int ni = 0; ni < 4; ni++) {
            const int c = n0 + wn * 32 + ni * 8 + s4 * 2;
            *(float2*)(C + (size_t)r0 * N + c)       = make_float2(acc[mi][ni][0], acc[mi][ni][1]);
            *(float2*)(C + (size_t)(r0 + 8) * N + c) = make_float2(acc[mi][ni][2], acc[mi][ni][3]);
        }
    }
}

// ---------------------------------------------------------------------------
// Transpose + tf32 rounding: out[C][R] = rna_tf32(in[R][C])^T
// Block (32,8), grid (C/32, R/32).
// ---------------------------------------------------------------------------
__global__ void transpose_round_kernel(const float* __restrict__ in, float* __restrict__ out,
                                       int R, int C)
{
    __shared__ float t[32][33];
    const int bx = blockIdx.x * 32, by = blockIdx.y * 32;
    const int tx = threadIdx.x, ty = threadIdx.y;
#pragma unroll
    for (int i = 0; i < 32; i += 8)
        t[ty + i][tx] = to_tf32(in[(size_t)(by + ty + i) * C + bx + tx]);
    __syncthreads();
#pragma unroll
    for (int i = 0; i < 32; i += 8)
        out[(size_t)(bx + ty + i) * R + by + tx] = t[tx][ty + i];
}

// ---------------------------------------------------------------------------
// RoPE table: cos/sin in double precision
// ---------------------------------------------------------------------------
__global__ void rope_table_kernel()
{
    int idx = blockIdx.x * blockDim.x + threadIdx.x;
    if (idx >= T_SEQ * (HD / 2)) return;
    int t = idx / (HD / 2);
    int i = idx % (HD / 2);
    double inv = pow(10000.0, -(double)(2 * i) / (double)HD);
    double ang = (double)t * inv;
    double s, c;
    sincos(ang, &s, &c);
    g_cos[idx] = (float)c;
    g_sin[idx] = (float)s;
}

// Apply RoPE in-place to tensor with layout (B*T, nheads*128)
__global__ void rope_apply_kernel(float* __restrict__ x, int nheads)
{
    int idx = blockIdx.x * blockDim.x + threadIdx.x;
    int pairs_per_row = nheads * (HD / 2);
    if (idx >= ROWS * pairs_per_row) return;
    int row = idx / pairs_per_row;
    int p = idx - row * pairs_per_row;
    int h = p / (HD / 2);
    int i = p - h * (HD / 2);
    int t = row & (T_SEQ - 1);
    float c = g_cos[t * (HD / 2) + i];
    float s = g_sin[t * (HD / 2) + i];
    float* base = x + (size_t)row * nheads * HD + h * HD + 2 * i;
    float x0 = base[0], x1 = base[1];
    base[0] = x0 * c - x1 * s;
    base[1] = x0 * s + x1 * c;
}

// ---------------------------------------------------------------------------
// Flash attention, fp32, causal, GQA (2 q heads per kv head). (unchanged)
// ---------------------------------------------------------------------------
__global__ __launch_bounds__(256) void attn_kernel()
{
    __shared__ float Ks[32 * 128];
    __shared__ float Vs[32 * 128];

    const int tid = threadIdx.x;
    const int w = tid >> 5, lane = tid & 31;
    const int rl = (w << 2) + (lane >> 3);   // local q row 0..31
    const int g = lane & 7;                  // 16-dim group 0..7

    const int qb = blockIdx.x;               // q tile index
    const int bh = blockIdx.y;
    const int b = bh >> 4, h = bh & 15;
    const int kh = h >> 1;                   // GQA: kv head
    const int qi = qb * 32 + rl;

    const float scale = 0.08838834764831845f;  // 128^-0.5

    float q[16], o[16];
    const float* qptr = g_Q + (size_t)(b * T_SEQ + qi) * QW + h * HD + g * 16;
#pragma unroll
    for (int j = 0; j < 16; j++) { q[j] = qptr[j] * scale; o[j] = 0.f; }

    float m = -INFINITY, l = 0.f;

    for (int t0 = 0; t0 <= qb; t0++) {
        const int k0 = t0 * 32;
        const float* Kb = g_K + (size_t)(b * T_SEQ + k0) * KW + kh * HD;
        const float* Vb = g_V + (size_t)(b * T_SEQ + k0) * KW + kh * HD;

        __syncthreads();
#pragma unroll
        for (int it = 0; it < 4; it++) {
            int idx = tid + it * 256;        // float4 index 0..1023
            int r = idx >> 5;
            int c = idx & 31;
            ((float4*)Ks)[idx] = *(const float4*)(Kb + (size_t)r * KW + c * 4);
            ((float4*)Vs)[idx] = *(const float4*)(Vb + (size_t)r * KW + c * 4);
        }
        __syncthreads();

        const bool diag = (t0 == qb);
        float sreg[4];
        float tmax = -INFINITY;

#pragma unroll
        for (int kk = 0; kk < 32; kk++) {
            const float4* kr = (const float4*)(Ks + kk * 128 + g * 16);
            float4 ka = kr[0], kb2 = kr[1], kc = kr[2], kd = kr[3];
            float s;
            s = q[0] * ka.x;
            s = fmaf(q[1],  ka.y,  s); s = fmaf(q[2],  ka.z,  s); s = fmaf(q[3],  ka.w,  s);
            s = fmaf(q[4],  kb2.x, s); s = fmaf(q[5],  kb2.y, s); s = fmaf(q[6],  kb2.z, s); s = fmaf(q[7],  kb2.w, s);
            s = fmaf(q[8],  kc.x,  s); s = fmaf(q[9],  kc.y,  s); s = fmaf(q[10], kc.z,  s); s = fmaf(q[11], kc.w,  s);
            s = fmaf(q[12], kd.x,  s); s = fmaf(q[13], kd.y,  s); s = fmaf(q[14], kd.z,  s); s = fmaf(q[15], kd.w,  s);
            s += __shfl_xor_sync(0xffffffffu, s, 1);
            s += __shfl_xor_sync(0xffffffffu, s, 2);
            s += __shfl_xor_sync(0xffffffffu, s, 4);
            if (diag && (k0 + kk > qi)) s = -INFINITY;
            if ((kk & 7) == g) sreg[kk >> 3] = s;
            tmax = fmaxf(tmax, s);
        }

        float mnew = fmaxf(m, tmax);
        float corr = __expf(m - mnew);
        l *= corr;
#pragma unroll
        for (int j = 0; j < 16; j++) o[j] *= corr;
        m = mnew;

#pragma unroll
        for (int kk = 0; kk < 32; kk++) {
            float s = __shfl_sync(0xffffffffu, sreg[kk >> 3], kk & 7, 8);
            float p = __expf(s - m);
            l += p;
            const float4* vr = (const float4*)(Vs + kk * 128 + g * 16);
            float4 va = vr[0], vb2 = vr[1], vc = vr[2], vd = vr[3];
            o[0]  = fmaf(p, va.x,  o[0]);  o[1]  = fmaf(p, va.y,  o[1]);
            o[2]  = fmaf(p, va.z,  o[2]);  o[3]  = fmaf(p, va.w,  o[3]);
            o[4]  = fmaf(p, vb2.x, o[4]);  o[5]  = fmaf(p, vb2.y, o[5]);
            o[6]  = fmaf(p, vb2.z, o[6]);  o[7]  = fmaf(p, vb2.w, o[7]);
            o[8]  = fmaf(p, vc.x,  o[8]);  o[9]  = fmaf(p, vc.y,  o[9]);
            o[10] = fmaf(p, vc.z,  o[10]); o[11] = fmaf(p, vc.w,  o[11]);
            o[12] = fmaf(p, vd.x,  o[12]); o[13] = fmaf(p, vd.y,  o[13]);
            o[14] = fmaf(p, vd.z,  o[14]); o[15] = fmaf(p, vd.w,  o[15]);
        }
    }

    const float inv = 1.f / l;
    float* outp = g_AO + (size_t)(b * T_SEQ + qi) * QW + h * HD + g * 16;
#pragma unroll
    for (int v4 = 0; v4 < 4; v4++) {
        float4 ov = make_float4(o[v4 * 4 + 0] * inv, o[v4 * 4 + 1] * inv,
                                o[v4 * 4 + 2] * inv, o[v4 * 4 + 3] * inv);
        *(float4*)(outp + v4 * 4) = ov;
    }
}

// ---------------------------------------------------------------------------
// kernel_launch: x, mask, wq, wk, wv, wo -> out (B,T,E) fp32
// ---------------------------------------------------------------------------
extern "C" void kernel_launch(void* const* d_in, const int* in_sizes, int n_in,
                              void* d_out, int out_size)
{
    const float* x  = (const float*)d_in[0];
    // d_in[1] = causal mask (unused: causality computed directly)
    const float* wq = (const float*)d_in[2];
    const float* wk = (const float*)d_in[3];
    const float* wv = (const float*)d_in[4];
    const float* wo = (const float*)d_in[5];
    float* out = (float*)d_out;

    float *Qp, *Kp, *Vp, *AOp, *WTp;
    cudaGetSymbolAddress((void**)&Qp,  g_Q);
    cudaGetSymbolAddress((void**)&Kp,  g_K);
    cudaGetSymbolAddress((void**)&Vp,  g_V);
    cudaGetSymbolAddress((void**)&AOp, g_AO);
    cudaGetSymbolAddress((void**)&WTp, g_WT);

    cudaFuncSetAttribute(gemm_mma, cudaFuncAttributeMaxDynamicSharedMemorySize, GEMM_SMEM);

    // Q = X @ Wq
    {
        dim3 tg(E_DIM / 32, E_DIM / 32);
        transpose_round_kernel<<<tg, dim3(32, 8)>>>(wq, WTp, E_DIM, QW);
        dim3 grid(QW / 128, ROWS / 128);
        gemm_mma<<<grid, 256, GEMM_SMEM>>>(x, WTp, Qp, ROWS, QW, E_DIM);
    }
    // K = X @ Wk
    {
        dim3 tg(KW / 32, E_DIM / 32);
        transpose_round_kernel<<<tg, dim3(32, 8)>>>(wk, WTp, E_DIM, KW);
        dim3 grid(KW / 128, ROWS / 128);
        gemm_mma<<<grid, 256, GEMM_SMEM>>>(x, WTp, Kp, ROWS, KW, E_DIM);
    }
    // V = X @ Wv
    {
        dim3 tg(KW / 32, E_DIM / 32);
        transpose_round_kernel<<<tg, dim3(32, 8)>>>(wv, WTp, E_DIM, KW);
        dim3 grid(KW / 128, ROWS / 128);
        gemm_mma<<<grid, 256, GEMM_SMEM>>>(x, WTp, Vp, ROWS, KW, E_DIM);
    }

    // RoPE
    {
        int n = T_SEQ * (HD / 2);
        rope_table_kernel<<<(n + 255) / 256, 256>>>();
        int nq = ROWS * NH * (HD / 2);
        rope_apply_kernel<<<(nq + 255) / 256, 256>>>(Qp, NH);
        int nk = ROWS * NKV * (HD / 2);
        rope_apply_kernel<<<(nk + 255) / 256, 256>>>(Kp, NKV);
    }

    // Attention
    {
        dim3 grid(T_SEQ / 32, B_SZ * NH);
        attn_kernel<<<grid, 256>>>();
    }

    // out = AO @ Wo
    {
        dim3 tg(E_DIM / 32, QW / 32);
        transpose_round_kernel<<<tg, dim3(32, 8)>>>(wo, WTp, QW, E_DIM);
        dim3 grid(E_DIM / 128, ROWS / 128);
        gemm_mma<<<grid, 256, GEMM_SMEM>>>(AOp, WTp, out, ROWS, E_DIM, E_DIM);
    }
}